// round 2
// baseline (speedup 1.0000x reference)
#include <cuda_runtime.h>
#include <math_constants.h>

#define B_ 4
#define S_ 512
#define D_ 768
#define MAX_LEN_ 10
#define LEN_EMB_ 25
#define NUM_LABELS_ 9
#define N_ (S_ * MAX_LEN_)   // 5120

// len_logits[L-1][c] = len_emb_table[L-1] . W[768:, c] + b[c]
__device__ float g_len_logits[MAX_LEN_ * NUM_LABELS_];
// Transposed W head: Wt[c][d] = W[d][c]  (coalesced register loads in main kernel)
__device__ __align__(16) float g_Wt[NUM_LABELS_][D_];

__global__ void prep_kernel(const float* __restrict__ len_emb_table,
                            const float* __restrict__ W,
                            const float* __restrict__ bvec) {
    int i = blockIdx.x * 256 + threadIdx.x;
    if (i < NUM_LABELS_ * D_) {
        int c = i / D_;
        int d = i % D_;
        g_Wt[c][d] = W[(size_t)d * NUM_LABELS_ + c];
    }
    if (blockIdx.x == 0 && threadIdx.x < MAX_LEN_ * NUM_LABELS_) {
        int L = threadIdx.x / NUM_LABELS_;
        int c = threadIdx.x % NUM_LABELS_;
        float s = bvec[c];
        #pragma unroll
        for (int k = 0; k < LEN_EMB_; k++) {
            s = fmaf(len_emb_table[L * LEN_EMB_ + k], W[(D_ + k) * NUM_LABELS_ + c], s);
        }
        g_len_logits[threadIdx.x] = s;
    }
}

__device__ __forceinline__ float4 max4(float4 a, float4 b) {
    float4 r;
    r.x = fmaxf(a.x, b.x); r.y = fmaxf(a.y, b.y);
    r.z = fmaxf(a.z, b.z); r.w = fmaxf(a.w, b.w);
    return r;
}
__device__ __forceinline__ float2 max2(float2 a, float2 b) {
    float2 r; r.x = fmaxf(a.x, b.x); r.y = fmaxf(a.y, b.y); return r;
}

// One 128-thread block per (batch, start, column-triple).
// Thread t owns dims [4t, 4t+4) (float4) and [512+2t, 512+2t+2) (float2): 6 dims.
// ~50 regs/thread -> 16 blocks/SM resident (full 2048-thread occupancy).
__global__ __launch_bounds__(128, 12) void span_ner_kernel(
    const float* __restrict__ we,       // [B, S, D]
    const int*   __restrict__ starts,   // [B, N]
    const int*   __restrict__ lens,     // [B, N]
    float*       __restrict__ out)      // [B, N, 9]
{
    __shared__ float red[2][4][3];      // [j parity][warp][col]

    const int tid  = threadIdx.x;
    const int lane = tid & 31;
    const int wid  = tid >> 5;

    const int task   = blockIdx.x;
    const int csplit = task % 3;
    const int bs     = task / 3;
    const int b = bs >> 9;              // /512
    const int s = bs & (S_ - 1);
    const int c0 = csplit * 3;

    // Per-thread W slice (coalesced from transposed table): 18 floats
    float4 w4[3];
    float2 w2[3];
    #pragma unroll
    for (int c = 0; c < 3; c++) {
        w4[c] = *(const float4*)&g_Wt[c0 + c][4 * tid];
        w2[c] = *(const float2*)&g_Wt[c0 + c][512 + 2 * tid];
    }

    const size_t bn = (size_t)b * N_ + (size_t)s * MAX_LEN_;
    const int start = starts[bn];
    const int* lensp = lens + bn;
    const int Lmax = lensp[MAX_LEN_ - 1];

    const float* base = we + ((size_t)b * S_ + start) * D_;

    float4 m4 = make_float4(-CUDART_INF_F, -CUDART_INF_F, -CUDART_INF_F, -CUDART_INF_F);
    float2 m2 = make_float2(-CUDART_INF_F, -CUDART_INF_F);

    // prefetch row 0
    float4 p4 = *(const float4*)(base + 4 * tid);
    float2 p2 = *(const float2*)(base + 512 + 2 * tid);

    int covered = 0;
    #pragma unroll 1
    for (int j = 0; j < MAX_LEN_; j++) {
        const int L = lensp[j];         // uniform across block, nondecreasing
        while (covered < L) {
            float4 c4 = p4;
            float2 c2 = p2;
            covered++;
            if (covered < Lmax) {
                const float* rowp = base + (size_t)covered * D_;
                p4 = *(const float4*)(rowp + 4 * tid);
                p2 = *(const float2*)(rowp + 512 + 2 * tid);
            }
            m4 = max4(m4, c4);
            m2 = max2(m2, c2);
        }

        // partial dot: 6 dims x 3 columns = 18 FMA
        float a0, a1, a2;
        a0 = m4.x * w4[0].x; a1 = m4.x * w4[1].x; a2 = m4.x * w4[2].x;
        a0 = fmaf(m4.y, w4[0].y, a0); a1 = fmaf(m4.y, w4[1].y, a1); a2 = fmaf(m4.y, w4[2].y, a2);
        a0 = fmaf(m4.z, w4[0].z, a0); a1 = fmaf(m4.z, w4[1].z, a1); a2 = fmaf(m4.z, w4[2].z, a2);
        a0 = fmaf(m4.w, w4[0].w, a0); a1 = fmaf(m4.w, w4[1].w, a1); a2 = fmaf(m4.w, w4[2].w, a2);
        a0 = fmaf(m2.x, w2[0].x, a0); a1 = fmaf(m2.x, w2[1].x, a1); a2 = fmaf(m2.x, w2[2].x, a2);
        a0 = fmaf(m2.y, w2[0].y, a0); a1 = fmaf(m2.y, w2[1].y, a1); a2 = fmaf(m2.y, w2[2].y, a2);

        // warp butterfly reduce (3 parallel 5-deep chains)
        #pragma unroll
        for (int off = 16; off > 0; off >>= 1) {
            a0 += __shfl_xor_sync(0xFFFFFFFFu, a0, off);
            a1 += __shfl_xor_sync(0xFFFFFFFFu, a1, off);
            a2 += __shfl_xor_sync(0xFFFFFFFFu, a2, off);
        }

        // cross-warp combine via double-buffered smem (1 barrier per j)
        const int par = j & 1;
        if (lane < 3) {
            red[par][wid][lane] = (lane == 0) ? a0 : ((lane == 1) ? a1 : a2);
        }
        __syncthreads();
        if (tid < 3) {
            float ssum = red[par][0][tid] + red[par][1][tid]
                       + red[par][2][tid] + red[par][3][tid];
            out[(bn + j) * NUM_LABELS_ + c0 + tid] =
                ssum + g_len_logits[(L - 1) * NUM_LABELS_ + c0 + tid];
        }
    }
}

extern "C" void kernel_launch(void* const* d_in, const int* in_sizes, int n_in,
                              void* d_out, int out_size) {
    const float* we     = (const float*)d_in[0];   // word_embeddings [B,S,D]
    const int*   starts = (const int*)d_in[1];     // span_starts [B,N]
    const int*   lens   = (const int*)d_in[2];     // span_lens [B,N]
    const float* let    = (const float*)d_in[3];   // len_emb_table [MAX_LEN, LEN_EMB]
    const float* W      = (const float*)d_in[4];   // W [D+LEN_EMB, 9]
    const float* bvec   = (const float*)d_in[5];   // b [9]
    float* out = (float*)d_out;

    prep_kernel<<<(NUM_LABELS_ * D_ + 255) / 256, 256>>>(let, W, bvec);

    const int blocks = B_ * S_ * 3;                // 6144 blocks, 128 threads each
    span_ner_kernel<<<blocks, 128>>>(we, starts, lens, out);
}

// round 4
// speedup vs baseline: 1.7301x; 1.7301x over previous
#include <cuda_runtime.h>
#include <math_constants.h>

#define B_ 4
#define S_ 512
#define D_ 768
#define MAX_LEN_ 10
#define LEN_EMB_ 25
#define NUM_LABELS_ 9
#define N_ (S_ * MAX_LEN_)   // 5120

// len_logits[L-1][c] = len_emb_table[L-1] . W[768:, c] + b[c]
__device__ float g_len_logits[MAX_LEN_ * NUM_LABELS_];
// Transposed W head: Wt[c][d] = W[d][c]
__device__ __align__(16) float g_Wt[NUM_LABELS_][D_];

__global__ void prep_kernel(const float* __restrict__ len_emb_table,
                            const float* __restrict__ W,
                            const float* __restrict__ bvec) {
    int i = blockIdx.x * 256 + threadIdx.x;
    if (i < NUM_LABELS_ * D_) {
        int c = i / D_;
        int d = i % D_;
        g_Wt[c][d] = W[(size_t)d * NUM_LABELS_ + c];
    }
    if (blockIdx.x == 0 && threadIdx.x < MAX_LEN_ * NUM_LABELS_) {
        int L = threadIdx.x / NUM_LABELS_;
        int c = threadIdx.x % NUM_LABELS_;
        float s = bvec[c];
        #pragma unroll
        for (int k = 0; k < LEN_EMB_; k++) {
            s = fmaf(len_emb_table[L * LEN_EMB_ + k], W[(D_ + k) * NUM_LABELS_ + c], s);
        }
        g_len_logits[threadIdx.x] = s;
    }
}

__device__ __forceinline__ float4 max4(float4 a, float4 b) {
    float4 r;
    r.x = fmaxf(a.x, b.x); r.y = fmaxf(a.y, b.y);
    r.z = fmaxf(a.z, b.z); r.w = fmaxf(a.w, b.w);
    return r;
}

// One 96-thread block per (batch, start).
// Phase 1: prefix-max pooling into smem (each we row read ONCE per block).
// Phase 2: warp w computes columns [3w, 3w+3) for all 10 spans; W slice in
//          registers, pooled read conflict-free from smem, 15-shfl reduce per j.
__global__ __launch_bounds__(96) void span_ner_kernel(
    const float* __restrict__ we,       // [B, S, D]
    const int*   __restrict__ starts,   // [B, N]
    const int*   __restrict__ lens,     // [B, N]
    float*       __restrict__ out)      // [B, N, 9]
{
    __shared__ float pooled[MAX_LEN_][D_];   // 30.7 KB

    const int tid  = threadIdx.x;
    const int lane = tid & 31;
    const int wid  = tid >> 5;

    const int bs = blockIdx.x;
    const int b = bs >> 9;               // /512
    const int s = bs & (S_ - 1);

    const size_t bn = (size_t)b * N_ + (size_t)s * MAX_LEN_;
    const int start = starts[bn];
    const int* lensp = lens + bn;

    int Ls[MAX_LEN_];
    #pragma unroll
    for (int j = 0; j < MAX_LEN_; j++) Ls[j] = __ldg(lensp + j);
    const int Lmax = Ls[MAX_LEN_ - 1];

    const float* base = we + ((size_t)b * S_ + start) * D_;

    // ---- Phase 1: pooling. Thread owns dims [4t,4t+4) and [384+4t, 384+4t+4).
    {
        float4 mA = make_float4(-CUDART_INF_F, -CUDART_INF_F, -CUDART_INF_F, -CUDART_INF_F);
        float4 mB = mA;
        int jp = 0;
        #pragma unroll 1
        for (int r = 0; r < Lmax; r++) {
            const float* rowp = base + (size_t)r * D_;
            float4 vA = *(const float4*)(rowp + 4 * tid);
            float4 vB = *(const float4*)(rowp + 384 + 4 * tid);
            mA = max4(mA, vA);
            mB = max4(mB, vB);
            // store prefix max for every span whose length == r+1
            while (jp < MAX_LEN_ && Ls[jp] == r + 1) {
                *(float4*)&pooled[jp][4 * tid]       = mA;
                *(float4*)&pooled[jp][384 + 4 * tid] = mB;
                jp++;
            }
        }
    }
    __syncthreads();

    // ---- Phase 2: warp wid handles columns c0..c0+2 for all j.
    const int c0 = wid * 3;

    // Lane owns dims d = 4*(lane + 32k), k in [0,6). W slice: 72 regs, coalesced load.
    float4 Wr[6][3];
    #pragma unroll
    for (int k = 0; k < 6; k++) {
        #pragma unroll
        for (int t = 0; t < 3; t++) {
            Wr[k][t] = *(const float4*)&g_Wt[c0 + t][4 * (lane + 32 * k)];
        }
    }

    #pragma unroll 1
    for (int j = 0; j < MAX_LEN_; j++) {
        float a0 = 0.f, a1 = 0.f, a2 = 0.f;
        #pragma unroll
        for (int k = 0; k < 6; k++) {
            float4 v = *(const float4*)&pooled[j][4 * (lane + 32 * k)];
            a0 = fmaf(v.x, Wr[k][0].x, a0); a1 = fmaf(v.x, Wr[k][1].x, a1); a2 = fmaf(v.x, Wr[k][2].x, a2);
            a0 = fmaf(v.y, Wr[k][0].y, a0); a1 = fmaf(v.y, Wr[k][1].y, a1); a2 = fmaf(v.y, Wr[k][2].y, a2);
            a0 = fmaf(v.z, Wr[k][0].z, a0); a1 = fmaf(v.z, Wr[k][1].z, a1); a2 = fmaf(v.z, Wr[k][2].z, a2);
            a0 = fmaf(v.w, Wr[k][0].w, a0); a1 = fmaf(v.w, Wr[k][1].w, a1); a2 = fmaf(v.w, Wr[k][2].w, a2);
        }

        #pragma unroll
        for (int off = 16; off > 0; off >>= 1) {
            a0 += __shfl_xor_sync(0xFFFFFFFFu, a0, off);
            a1 += __shfl_xor_sync(0xFFFFFFFFu, a1, off);
            a2 += __shfl_xor_sync(0xFFFFFFFFu, a2, off);
        }

        if (lane < 3) {
            const float av = (lane == 0) ? a0 : ((lane == 1) ? a1 : a2);
            const int c = c0 + lane;
            out[(bn + j) * NUM_LABELS_ + c] = av + g_len_logits[(Ls[j] - 1) * NUM_LABELS_ + c];
        }
    }
}

extern "C" void kernel_launch(void* const* d_in, const int* in_sizes, int n_in,
                              void* d_out, int out_size) {
    const float* we     = (const float*)d_in[0];   // word_embeddings [B,S,D]
    const int*   starts = (const int*)d_in[1];     // span_starts [B,N]
    const int*   lens   = (const int*)d_in[2];     // span_lens [B,N]
    const float* let    = (const float*)d_in[3];   // len_emb_table [MAX_LEN, LEN_EMB]
    const float* W      = (const float*)d_in[4];   // W [D+LEN_EMB, 9]
    const float* bvec   = (const float*)d_in[5];   // b [9]
    float* out = (float*)d_out;

    prep_kernel<<<(NUM_LABELS_ * D_ + 255) / 256, 256>>>(let, W, bvec);

    span_ner_kernel<<<B_ * S_, 96>>>(we, starts, lens, out);
}

// round 5
// speedup vs baseline: 2.7454x; 1.5869x over previous
#include <cuda_runtime.h>
#include <math_constants.h>

#define B_ 4
#define S_ 512
#define D_ 768
#define MAX_LEN_ 10
#define LEN_EMB_ 25
#define NUM_LABELS_ 9
#define N_ (S_ * MAX_LEN_)   // 5120

// len_logits[L-1][c] = len_emb_table[L-1] . W[768:, c] + b[c]
__device__ float g_len_logits[MAX_LEN_ * NUM_LABELS_];
// Transposed W head: Wt[c][d] = W[d][c]
__device__ __align__(16) float g_Wt[NUM_LABELS_][D_];

__global__ void prep_kernel(const float* __restrict__ len_emb_table,
                            const float* __restrict__ W,
                            const float* __restrict__ bvec) {
    int i = blockIdx.x * 256 + threadIdx.x;
    if (i < NUM_LABELS_ * D_) {
        int c = i / D_;
        int d = i % D_;
        g_Wt[c][d] = W[(size_t)d * NUM_LABELS_ + c];
    }
    if (blockIdx.x == 0 && threadIdx.x < MAX_LEN_ * NUM_LABELS_) {
        int L = threadIdx.x / NUM_LABELS_;
        int c = threadIdx.x % NUM_LABELS_;
        float s = bvec[c];
        #pragma unroll
        for (int k = 0; k < LEN_EMB_; k++) {
            s = fmaf(len_emb_table[L * LEN_EMB_ + k], W[(D_ + k) * NUM_LABELS_ + c], s);
        }
        g_len_logits[threadIdx.x] = s;
    }
}

__device__ __forceinline__ float4 max4(float4 a, float4 b) {
    float4 r;
    r.x = fmaxf(a.x, b.x); r.y = fmaxf(a.y, b.y);
    r.z = fmaxf(a.z, b.z); r.w = fmaxf(a.w, b.w);
    return r;
}

// One 96-thread block per (batch, start).
// Phase 1: fully-unrolled clamped prefix-max pooling into smem (MLP=20 loads).
// Phase 2: warp w -> columns [3w,3w+3); 30 register accumulators (all j),
//          ONE smem transpose-reduction at the end. Zero shuffles.
__global__ __launch_bounds__(96, 5) void span_ner_kernel(
    const float* __restrict__ we,       // [B, S, D]
    const int*   __restrict__ starts,   // [B, N]
    const int*   __restrict__ lens,     // [B, N]
    float*       __restrict__ out)      // [B, N, 9]
{
    __shared__ float sm[MAX_LEN_ * D_];      // pooled[10][768]; tail reused as red[]

    const int tid  = threadIdx.x;
    const int lane = tid & 31;
    const int wid  = tid >> 5;

    const int bs = blockIdx.x;
    const int b = bs >> 9;               // /512
    const int s = bs & (S_ - 1);

    const size_t bn = (size_t)b * N_ + (size_t)s * MAX_LEN_;
    const int start = starts[bn];
    const int* lensp = lens + bn;
    const int Smax = S_ - start;         // >= 1

    const float* base = we + ((size_t)b * S_ + start) * D_;

    // ---- Phase 1: pooled[j] = max over rows 0..min(j, Smax-1).
    // Clamped duplicate rows are idempotent under max -> matches lens semantics.
    {
        float4 vA[MAX_LEN_], vB[MAX_LEN_];
        #pragma unroll
        for (int r = 0; r < MAX_LEN_; r++) {
            const int rc = (r < Smax - 1) ? r : (Smax - 1);
            const float* rowp = base + (size_t)rc * D_;
            vA[r] = *(const float4*)(rowp + 4 * tid);
            vB[r] = *(const float4*)(rowp + 384 + 4 * tid);
        }
        float4 mA = vA[0], mB = vB[0];
        *(float4*)&sm[0 * D_ + 4 * tid]       = mA;
        *(float4*)&sm[0 * D_ + 384 + 4 * tid] = mB;
        #pragma unroll
        for (int r = 1; r < MAX_LEN_; r++) {
            mA = max4(mA, vA[r]);
            mB = max4(mB, vB[r]);
            *(float4*)&sm[r * D_ + 4 * tid]       = mA;
            *(float4*)&sm[r * D_ + 384 + 4 * tid] = mB;
        }
    }
    __syncthreads();

    // ---- Phase 2: warp wid handles columns c0..c0+2 for all j.
    const int c0 = wid * 3;

    // Lane owns dims d = 4*(lane + 32k), k in [0,6). W slice: 72 regs, coalesced.
    float4 Wr[6][3];
    #pragma unroll
    for (int k = 0; k < 6; k++) {
        #pragma unroll
        for (int t = 0; t < 3; t++) {
            Wr[k][t] = *(const float4*)&g_Wt[c0 + t][4 * (lane + 32 * k)];
        }
    }

    float acc0[MAX_LEN_], acc1[MAX_LEN_], acc2[MAX_LEN_];
    #pragma unroll
    for (int j = 0; j < MAX_LEN_; j++) {
        float a0 = 0.f, a1 = 0.f, a2 = 0.f;
        #pragma unroll
        for (int k = 0; k < 6; k++) {
            float4 v = *(const float4*)&sm[j * D_ + 4 * (lane + 32 * k)];
            a0 = fmaf(v.x, Wr[k][0].x, a0); a1 = fmaf(v.x, Wr[k][1].x, a1); a2 = fmaf(v.x, Wr[k][2].x, a2);
            a0 = fmaf(v.y, Wr[k][0].y, a0); a1 = fmaf(v.y, Wr[k][1].y, a1); a2 = fmaf(v.y, Wr[k][2].y, a2);
            a0 = fmaf(v.z, Wr[k][0].z, a0); a1 = fmaf(v.z, Wr[k][1].z, a1); a2 = fmaf(v.z, Wr[k][2].z, a2);
            a0 = fmaf(v.w, Wr[k][0].w, a0); a1 = fmaf(v.w, Wr[k][1].w, a1); a2 = fmaf(v.w, Wr[k][2].w, a2);
        }
        acc0[j] = a0; acc1[j] = a1; acc2[j] = a2;
    }

    // all reads of pooled done -> safe to overlay red[] on sm
    __syncthreads();

    // Transpose-reduce: red rows stride 36 floats (16B aligned, conflict-free
    // for both the STS.32 writes and the per-lane LDS.128 row reads).
    float* redw = sm + wid * (30 * 36);
    #pragma unroll
    for (int j = 0; j < MAX_LEN_; j++) {
        redw[(3 * j + 0) * 36 + lane] = acc0[j];
        redw[(3 * j + 1) * 36 + lane] = acc1[j];
        redw[(3 * j + 2) * 36 + lane] = acc2[j];
    }
    __syncwarp();

    if (lane < 30) {
        const float4* rp = (const float4*)(redw + lane * 36);
        float4 s0 = rp[0], s1 = rp[1], s2 = rp[2], s3 = rp[3];
        float4 s4 = rp[4], s5 = rp[5], s6 = rp[6], s7 = rp[7];
        s0 = make_float4(s0.x + s4.x, s0.y + s4.y, s0.z + s4.z, s0.w + s4.w);
        s1 = make_float4(s1.x + s5.x, s1.y + s5.y, s1.z + s5.z, s1.w + s5.w);
        s2 = make_float4(s2.x + s6.x, s2.y + s6.y, s2.z + s6.z, s2.w + s6.w);
        s3 = make_float4(s3.x + s7.x, s3.y + s7.y, s3.z + s7.z, s3.w + s7.w);
        s0 = make_float4(s0.x + s2.x, s0.y + s2.y, s0.z + s2.z, s0.w + s2.w);
        s1 = make_float4(s1.x + s3.x, s1.y + s3.y, s1.z + s3.z, s1.w + s3.w);
        float tot = (s0.x + s1.x) + (s0.y + s1.y) + (s0.z + s1.z) + (s0.w + s1.w);

        const int j = lane / 3;
        const int t = lane - 3 * j;
        const int L = __ldg(lensp + j);
        out[(bn + j) * NUM_LABELS_ + c0 + t] =
            tot + g_len_logits[(L - 1) * NUM_LABELS_ + c0 + t];
    }
}

extern "C" void kernel_launch(void* const* d_in, const int* in_sizes, int n_in,
                              void* d_out, int out_size) {
    const float* we     = (const float*)d_in[0];   // word_embeddings [B,S,D]
    const int*   starts = (const int*)d_in[1];     // span_starts [B,N]
    const int*   lens   = (const int*)d_in[2];     // span_lens [B,N]
    const float* let    = (const float*)d_in[3];   // len_emb_table [MAX_LEN, LEN_EMB]
    const float* W      = (const float*)d_in[4];   // W [D+LEN_EMB, 9]
    const float* bvec   = (const float*)d_in[5];   // b [9]
    float* out = (float*)d_out;

    prep_kernel<<<(NUM_LABELS_ * D_ + 255) / 256, 256>>>(let, W, bvec);

    span_ner_kernel<<<B_ * S_, 96>>>(we, starts, lens, out);
}